// round 15
// baseline (speedup 1.0000x reference)
#include <cuda_runtime.h>
#include <cuda_bf16.h>
#include <cstdint>

#define HO 190
#define WO 190
#define XROW 8448                 // 66 cols x 128B per (slot,pass) row
#define XS_BYTES (4 * 2 * XROW)   // 67584
#define BF_OFF XS_BYTES
#define BF_BYTES 147456           // 36 ksteps x 16 ntiles x 32 lanes x 8B
#define DS_OFF (BF_OFF + BF_BYTES)
#define SMEM_TOTAL (DS_OFF + 64 * 68 * 4)   // 232448 = 227KB exactly
#define NBLK 148                  // persistent blocks (1/SM)
#define NU   (190 * 12)           // global row-units: 12 streams x 190 rows

typedef unsigned long long ull;

__device__ float g_Wd[64 * 9 * 64];                     // [o][tap][i]
__device__ unsigned g_B[36 * 16 * 32 * 2];              // b-frags, reg order
__device__ __align__(16) __nv_bfloat16 g_xh[4ull * 192 * 192 * 64]; // [b][h][w][i]
__device__ __align__(16) __nv_bfloat16 g_xl[4ull * 192 * 192 * 64];

__device__ __forceinline__ void cpa16(uint32_t d, const void* s) {
    asm volatile("cp.async.ca.shared.global [%0], [%1], 16;" :: "r"(d), "l"(s));
}
#define CPCOMMIT() asm volatile("cp.async.commit_group;")
#define CPWAIT0()  asm volatile("cp.async.wait_group 0;")

// ------------------------- prep kernels -------------------------
__global__ void k_zero() {
    int i = blockIdx.x * 1024 + threadIdx.x;
    if (i < 64 * 9 * 64) g_Wd[i] = 0.0f;
}
__global__ void k_scatter(const float* __restrict__ w, const int* __restrict__ cin,
                          const int* __restrict__ cout, int K) {
    int k = blockIdx.x * 256 + threadIdx.x;
    if (k < K) {
        int o = cout[k], i = cin[k];
#pragma unroll
        for (int t = 0; t < 9; t++)
            atomicAdd(&g_Wd[(o * 9 + t) * 64 + i], w[k * 9 + t]);
    }
}
// B-frags for mma.m16n8k16 (B col-major frag: lane holds n = lane/4,
// k = kstep*16 + (lane%4)*2 (+1), reg1 at k+8). n<64 -> bf16-hi(W), n>=64 -> lo.
__global__ void k_buildB() {
    int idx = blockIdx.x * 256 + threadIdx.x;   // 36*16*32 = 18432
    if (idx >= 18432) return;
    int lane = idx & 31, nt = (idx >> 5) & 15, ks = idx >> 9;
    int n = nt * 8 + (lane >> 2);
    int o = n & 63;
    bool lo = n >= 64;
    int kk = ks * 16 + (lane & 3) * 2;
#pragma unroll
    for (int rr = 0; rr < 2; rr++) {
        unsigned pk = 0;
#pragma unroll
        for (int e = 0; e < 2; e++) {
            int k = kk + rr * 8 + e;
            int tap = k >> 6, i = k & 63;
            float v = g_Wd[(o * 9 + tap) * 64 + i];
            __nv_bfloat16 h = __float2bfloat16(v);
            __nv_bfloat16 val = lo ? __float2bfloat16(v - __bfloat162float(h)) : h;
            pk |= (unsigned)__bfloat16_as_ushort(val) << (16 * e);
        }
        g_B[idx * 2 + rr] = pk;
    }
}
// x -> channel-last bf16 hi/lo: g_xh/g_xl[b][h][w][i], 128B per (h,w).
__global__ void k_transpose(const float* __restrict__ x) {
    __shared__ float sm[64 * 192];
    int h = blockIdx.x, b = blockIdx.y, t = threadIdx.x;
    for (int idx = t; idx < 64 * 192; idx += 256) {
        int i = idx / 192, w = idx % 192;
        sm[idx] = x[(((size_t)b * 64 + i) * 192 + h) * 192 + w];
    }
    __syncthreads();
    if (t < 192) {
        unsigned hv[32], lv[32];
#pragma unroll
        for (int q = 0; q < 32; q++) {
            float f0 = sm[(2 * q) * 192 + t], f1 = sm[(2 * q + 1) * 192 + t];
            __nv_bfloat16 h0 = __float2bfloat16(f0), h1 = __float2bfloat16(f1);
            __nv_bfloat16 l0 = __float2bfloat16(f0 - __bfloat162float(h0));
            __nv_bfloat16 l1 = __float2bfloat16(f1 - __bfloat162float(h1));
            hv[q] = (unsigned)__bfloat16_as_ushort(h0) | ((unsigned)__bfloat16_as_ushort(h1) << 16);
            lv[q] = (unsigned)__bfloat16_as_ushort(l0) | ((unsigned)__bfloat16_as_ushort(l1) << 16);
        }
        size_t base = (((size_t)b * 192 + h) * 192 + t) * 32;   // u32 units
        uint4* dh = (uint4*)g_xh + base / 4;
        uint4* dl = (uint4*)g_xl + base / 4;
#pragma unroll
        for (int q = 0; q < 8; q++) {
            dh[q] = make_uint4(hv[4*q], hv[4*q+1], hv[4*q+2], hv[4*q+3]);
            dl[q] = make_uint4(lv[4*q], lv[4*q+1], lv[4*q+2], lv[4*q+3]);
        }
    }
}

// ------------------------- conv kernel -------------------------
// Persistent: 148 blocks x 256 thr; each walks contiguous global row-units
// u = stream*190 + h, stream = (strip, batch) of 12; B-table resident.
__global__ __launch_bounds__(256, 1)
void conv_mma(const float* __restrict__ bias, float* __restrict__ out) {
    extern __shared__ __align__(16) char smem[];
    uint32_t sb = (uint32_t)__cvta_generic_to_shared(smem);
    int tid = threadIdx.x, lane = tid & 31, warp = tid >> 5;
    int wm = warp >> 1, wn = warp & 1;       // wm: m-strip 0..3, wn: n-half
    int pass = wm >> 1;                       // 0 = hi px, 1 = lo px
    int pbase = (wm & 1) * 32;                // pixel base within 64
    bool dead = (wm >= 2 && wn == 1);         // lo x Wl quadrant: skip mma

    // Stage full B-frag table (144 KB) once per block.
    for (int cc = tid; cc < BF_BYTES / 16; cc += 256)
        cpa16(sb + BF_OFF + cc * 16, (const char*)g_B + cc * 16);

#define STAGE(hh) do {                                                         \
        int _s = (hh) & 3;                                                     \
        const __nv_bfloat16* s0 = xh + (((size_t)(hh)) * 192 + w0) * 64;       \
        const __nv_bfloat16* s1 = xl + (((size_t)(hh)) * 192 + w0) * 64;       \
        for (int cc = tid; cc < 528; cc += 256) {                              \
            int ws_ = cc >> 3, j = cc & 7;                                     \
            uint32_t dof = (uint32_t)(ws_ * 128 + ((j ^ (ws_ & 7)) * 16));     \
            cpa16(sb + (uint32_t)((_s * 2 + 0) * XROW) + dof,                  \
                  (const char*)s0 + ws_ * 128 + j * 16);                       \
            cpa16(sb + (uint32_t)((_s * 2 + 1) * XROW) + dof,                  \
                  (const char*)s1 + ws_ * 128 + j * 16);                       \
        } } while (0)

    float* Ds = (float*)(smem + DS_OFF);     // [64 px][68] fp32

    int u  = (NU * blockIdx.x) / NBLK;
    int u1 = (NU * (blockIdx.x + 1)) / NBLK;

    while (u < u1) {
        int s = u / 190;
        int h = u - s * 190;
        int strip = s % 3, b = s / 3;
        int w0 = (strip == 0) ? 0 : (strip == 1 ? 64 : 126);
        const __nv_bfloat16* xh = g_xh + (size_t)b * 192 * 192 * 64;
        const __nv_bfloat16* xl = g_xl + (size_t)b * 192 * 192 * 64;

        STAGE(h); STAGE(h + 1); STAGE(h + 2);
        CPCOMMIT();

        int hend = u1 - s * 190; if (hend > 190) hend = 190;
        for (; h < hend; ++h, ++u) {
            CPWAIT0();
            __syncthreads();
            if (h + 3 <= 191) STAGE(h + 3);
            CPCOMMIT();

            float acc[2][8][4];
#pragma unroll
            for (int mt = 0; mt < 2; mt++)
#pragma unroll
                for (int nt = 0; nt < 8; nt++)
#pragma unroll
                    for (int e = 0; e < 4; e++) acc[mt][nt][e] = 0.0f;

            if (!dead) {
#pragma unroll
                for (int tap = 0; tap < 9; tap++) {
                    const int dh = tap / 3, dw = tap % 3;
                    int slot = (h + dh) & 3;
                    uint32_t arow = sb + (uint32_t)((slot * 2 + pass) * XROW);
#pragma unroll
                    for (int sub = 0; sub < 4; sub++) {
                        int ks = tap * 4 + sub;
                        unsigned bf[8][2];
#pragma unroll
                        for (int nt = 0; nt < 8; nt++) {
                            uint2 bv = *(const uint2*)(smem + BF_OFF +
                                (((size_t)(ks * 16 + wn * 8 + nt) * 32 + lane) << 3));
                            bf[nt][0] = bv.x; bf[nt][1] = bv.y;
                        }
                        unsigned af[2][4];
#pragma unroll
                        for (int mt = 0; mt < 2; mt++) {
                            int px = pbase + mt * 16 + (lane & 15);
                            int wl = px + dw;
                            int kc = lane >> 4;
                            uint32_t ad = arow + (uint32_t)(wl * 128 +
                                          (((sub * 2 + kc) ^ (wl & 7)) * 16));
                            asm volatile(
                                "ldmatrix.sync.aligned.m8n8.x4.shared.b16 {%0,%1,%2,%3}, [%4];"
                                : "=r"(af[mt][0]), "=r"(af[mt][1]),
                                  "=r"(af[mt][2]), "=r"(af[mt][3]) : "r"(ad));
                        }
#pragma unroll
                        for (int mt = 0; mt < 2; mt++)
#pragma unroll
                            for (int nt = 0; nt < 8; nt++)
                                asm volatile(
                                    "mma.sync.aligned.m16n8k16.row.col.f32.bf16.bf16.f32 "
                                    "{%0,%1,%2,%3}, {%4,%5,%6,%7}, {%8,%9}, {%0,%1,%2,%3};"
                                    : "+f"(acc[mt][nt][0]), "+f"(acc[mt][nt][1]),
                                      "+f"(acc[mt][nt][2]), "+f"(acc[mt][nt][3])
                                    : "r"(af[mt][0]), "r"(af[mt][1]),
                                      "r"(af[mt][2]), "r"(af[mt][3]),
                                      "r"(bf[nt][0]), "r"(bf[nt][1]));
                    }
                }
            }

            // Epilogue: y = D[hi,Wh] + D[hi,Wl] + D[lo,Wh].
#define FRAG_LOOP(...)                                                         \
            _Pragma("unroll")                                                  \
            for (int mt = 0; mt < 2; mt++) {                                   \
                int r0 = pbase + mt * 16 + (lane >> 2);                        \
                _Pragma("unroll")                                              \
                for (int nt = 0; nt < 8; nt++) {                               \
                    int c = nt * 8 + (lane & 3) * 2;                           \
                    float* q0 = &Ds[r0 * 68 + c];                              \
                    float* q1 = &Ds[(r0 + 8) * 68 + c];                        \
                    __VA_ARGS__;                                               \
                }                                                              \
            }
            if (wm < 2 && wn == 0)   // hi x Wh : plain store
                FRAG_LOOP(*(float2*)q0 = make_float2(acc[mt][nt][0], acc[mt][nt][1]);
                          *(float2*)q1 = make_float2(acc[mt][nt][2], acc[mt][nt][3]));
            __syncthreads();
            if ((wm < 2 && wn == 1) || (wm >= 2 && wn == 0))  // both adds concurrent
                FRAG_LOOP(atomicAdd(q0, acc[mt][nt][0]);
                          atomicAdd(q0 + 1, acc[mt][nt][1]);
                          atomicAdd(q1, acc[mt][nt][2]);
                          atomicAdd(q1 + 1, acc[mt][nt][3]));
            __syncthreads();

            {
                int o = tid >> 2, px0 = (tid & 3) * 16;
                float bv = bias[o];
                float* op = out + (((size_t)(b * 64 + o)) * HO + h) * WO + w0 + px0;
#pragma unroll
                for (int q = 0; q < 16; q += 2) {
                    float2 v;
                    v.x = Ds[(px0 + q) * 68 + o] + bv;
                    v.y = Ds[(px0 + q + 1) * 68 + o] + bv;
                    *(float2*)(op + q) = v;
                }
            }
            __syncthreads();   // Dstage free before next row
        }
    }
}

// ---------------------------------------------------------------------------
extern "C" void kernel_launch(void* const* d_in, const int* in_sizes, int n_in,
                              void* d_out, int out_size) {
    const float* x    = (const float*)d_in[0];
    const float* w    = (const float*)d_in[1];
    const float* bias = (const float*)d_in[2];
    const int*   cin  = (const int*)d_in[3];
    const int*   cout = (const int*)d_in[4];
    int K = in_sizes[3];
    int B = in_sizes[0] / (64 * 192 * 192);

    cudaFuncSetAttribute(conv_mma, cudaFuncAttributeMaxDynamicSharedMemorySize,
                         SMEM_TOTAL);

    k_zero<<<(64 * 9 * 64 + 1023) / 1024, 1024>>>();
    k_scatter<<<(K + 255) / 256, 256>>>(w, cin, cout, K);
    k_buildB<<<(18432 + 255) / 256, 256>>>();
    dim3 tg(192, B);
    k_transpose<<<tg, 256>>>(x);
    conv_mma<<<NBLK, 256, SMEM_TOTAL>>>(bias, (float*)d_out);
}

// round 16
// speedup vs baseline: 1.0510x; 1.0510x over previous
#include <cuda_runtime.h>
#include <cuda_bf16.h>
#include <cstdint>

#define HO 190
#define WO 190
#define XROW 8448                 // 66 cols x 128B per (slot,pass) row
#define XS_BYTES (4 * 2 * XROW)   // 67584
#define DS_OFF XS_BYTES
#define SMEM_TOTAL (DS_OFF + 64 * 68 * 4)   // 84992 B -> 2 CTAs/SM

typedef unsigned long long ull;

__device__ float g_Wd[64 * 9 * 64];                     // [o][tap][i]
__device__ __align__(16) unsigned g_B[36 * 16 * 32 * 2]; // b-frags, reg order
__device__ __align__(16) __nv_bfloat16 g_xh[4ull * 192 * 192 * 64]; // [b][h][w][i]
__device__ __align__(16) __nv_bfloat16 g_xl[4ull * 192 * 192 * 64];

__device__ __forceinline__ void cpa16(uint32_t d, const void* s) {
    asm volatile("cp.async.ca.shared.global [%0], [%1], 16;" :: "r"(d), "l"(s));
}
#define CPCOMMIT() asm volatile("cp.async.commit_group;")
#define CPWAIT0()  asm volatile("cp.async.wait_group 0;")

// ------------------------- prep kernels -------------------------
__global__ void k_zero() {
    int i = blockIdx.x * 1024 + threadIdx.x;
    if (i < 64 * 9 * 64) g_Wd[i] = 0.0f;
}
__global__ void k_scatter(const float* __restrict__ w, const int* __restrict__ cin,
                          const int* __restrict__ cout, int K) {
    int k = blockIdx.x * 256 + threadIdx.x;
    if (k < K) {
        int o = cout[k], i = cin[k];
#pragma unroll
        for (int t = 0; t < 9; t++)
            atomicAdd(&g_Wd[(o * 9 + t) * 64 + i], w[k * 9 + t]);
    }
}
// B-frags for mma.m16n8k16 (B col-major frag: lane holds n = lane/4,
// k = kstep*16 + (lane%4)*2 (+1), reg1 at k+8). n<64 -> bf16-hi(W), n>=64 -> lo.
__global__ void k_buildB() {
    int idx = blockIdx.x * 256 + threadIdx.x;   // 36*16*32 = 18432
    if (idx >= 18432) return;
    int lane = idx & 31, nt = (idx >> 5) & 15, ks = idx >> 9;
    int n = nt * 8 + (lane >> 2);
    int o = n & 63;
    bool lo = n >= 64;
    int kk = ks * 16 + (lane & 3) * 2;
#pragma unroll
    for (int rr = 0; rr < 2; rr++) {
        unsigned pk = 0;
#pragma unroll
        for (int e = 0; e < 2; e++) {
            int k = kk + rr * 8 + e;
            int tap = k >> 6, i = k & 63;
            float v = g_Wd[(o * 9 + tap) * 64 + i];
            __nv_bfloat16 h = __float2bfloat16(v);
            __nv_bfloat16 val = lo ? __float2bfloat16(v - __bfloat162float(h)) : h;
            pk |= (unsigned)__bfloat16_as_ushort(val) << (16 * e);
        }
        g_B[idx * 2 + rr] = pk;
    }
}
// x -> channel-last bf16 hi/lo: g_xh/g_xl[b][h][w][i], 128B per (h,w).
__global__ void k_transpose(const float* __restrict__ x) {
    __shared__ float sm[64 * 192];
    int h = blockIdx.x, b = blockIdx.y, t = threadIdx.x;
    for (int idx = t; idx < 64 * 192; idx += 256) {
        int i = idx / 192, w = idx % 192;
        sm[idx] = x[(((size_t)b * 64 + i) * 192 + h) * 192 + w];
    }
    __syncthreads();
    if (t < 192) {
        unsigned hv[32], lv[32];
#pragma unroll
        for (int q = 0; q < 32; q++) {
            float f0 = sm[(2 * q) * 192 + t], f1 = sm[(2 * q + 1) * 192 + t];
            __nv_bfloat16 h0 = __float2bfloat16(f0), h1 = __float2bfloat16(f1);
            __nv_bfloat16 l0 = __float2bfloat16(f0 - __bfloat162float(h0));
            __nv_bfloat16 l1 = __float2bfloat16(f1 - __bfloat162float(h1));
            hv[q] = (unsigned)__bfloat16_as_ushort(h0) | ((unsigned)__bfloat16_as_ushort(h1) << 16);
            lv[q] = (unsigned)__bfloat16_as_ushort(l0) | ((unsigned)__bfloat16_as_ushort(l1) << 16);
        }
        size_t base = (((size_t)b * 192 + h) * 192 + t) * 32;   // u32 units
        uint4* dh = (uint4*)g_xh + base / 4;
        uint4* dl = (uint4*)g_xl + base / 4;
#pragma unroll
        for (int q = 0; q < 8; q++) {
            dh[q] = make_uint4(hv[4*q], hv[4*q+1], hv[4*q+2], hv[4*q+3]);
            dl[q] = make_uint4(lv[4*q], lv[4*q+1], lv[4*q+2], lv[4*q+3]);
        }
    }
}

// ------------------------- conv kernel -------------------------
// grid (3, 19, 4): x = w-strip {0,64,126}, y = 10-row h chunk, z = batch.
// 256 thr / 8 warps; B-frags read from gmem (L2-resident); 2 CTAs/SM.
__global__ __launch_bounds__(256, 2)
void conv_mma(const float* __restrict__ bias, float* __restrict__ out) {
    extern __shared__ __align__(16) char smem[];
    uint32_t sb = (uint32_t)__cvta_generic_to_shared(smem);
    int tid = threadIdx.x, lane = tid & 31, warp = tid >> 5;
    int wm = warp >> 1, wn = warp & 1;       // wm: m-strip 0..3, wn: n-half
    int pass = wm >> 1;                       // 0 = hi px, 1 = lo px
    int pbase = (wm & 1) * 32;                // pixel base within 64
    bool dead = (wm >= 2 && wn == 1);         // lo x Wl quadrant: skip mma

    int b = blockIdx.z, h0 = blockIdx.y * 10;
    int w0 = (blockIdx.x == 0) ? 0 : (blockIdx.x == 1 ? 64 : 126);

    const __nv_bfloat16* xh = g_xh + (size_t)b * 192 * 192 * 64;
    const __nv_bfloat16* xl = g_xl + (size_t)b * 192 * 192 * 64;
    const uint2* gB2 = (const uint2*)g_B;     // frag (ks,nt): 32 lanes x 8B

    // Stage one (h-row, both passes): 66 cols x 8 chunks, XOR-swizzled.
#define STAGE(hh) do {                                                         \
        int _s = (hh) & 3;                                                     \
        const __nv_bfloat16* s0 = xh + (((size_t)(hh)) * 192 + w0) * 64;       \
        const __nv_bfloat16* s1 = xl + (((size_t)(hh)) * 192 + w0) * 64;       \
        for (int cc = tid; cc < 528; cc += 256) {                              \
            int ws_ = cc >> 3, j = cc & 7;                                     \
            uint32_t dof = (uint32_t)(ws_ * 128 + ((j ^ (ws_ & 7)) * 16));     \
            cpa16(sb + (uint32_t)((_s * 2 + 0) * XROW) + dof,                  \
                  (const char*)s0 + ws_ * 128 + j * 16);                       \
            cpa16(sb + (uint32_t)((_s * 2 + 1) * XROW) + dof,                  \
                  (const char*)s1 + ws_ * 128 + j * 16);                       \
        } } while (0)

    STAGE(h0); STAGE(h0 + 1); STAGE(h0 + 2);
    CPCOMMIT();

    float* Ds = (float*)(smem + DS_OFF);     // [64 px][68] fp32

    for (int r = 0; r < 10; r++) {
        int h = h0 + r;
        CPWAIT0();
        __syncthreads();
        if (r < 9) STAGE(h + 3);             // overwrites slot (h-1)&3 (free)
        CPCOMMIT();

        float acc[2][8][4];
#pragma unroll
        for (int mt = 0; mt < 2; mt++)
#pragma unroll
            for (int nt = 0; nt < 8; nt++)
#pragma unroll
                for (int e = 0; e < 4; e++) acc[mt][nt][e] = 0.0f;

        if (!dead) {
#pragma unroll
            for (int tap = 0; tap < 9; tap++) {
                const int dh = tap / 3, dw = tap % 3;
                int slot = (h + dh) & 3;
                uint32_t arow = sb + (uint32_t)((slot * 2 + pass) * XROW);
#pragma unroll
                for (int sub = 0; sub < 4; sub++) {
                    int ks = tap * 4 + sub;
                    // B frags from gmem (L2-resident, coalesced 256B/warp).
                    unsigned bf[8][2];
#pragma unroll
                    for (int nt = 0; nt < 8; nt++) {
                        uint2 bv = __ldg(&gB2[(size_t)(ks * 16 + wn * 8 + nt) * 32 + lane]);
                        bf[nt][0] = bv.x; bf[nt][1] = bv.y;
                    }
                    // A frags via ldmatrix.x4 (m16k16 each).
                    unsigned af[2][4];
#pragma unroll
                    for (int mt = 0; mt < 2; mt++) {
                        int px = pbase + mt * 16 + (lane & 15);
                        int wl = px + dw;
                        int kc = lane >> 4;
                        uint32_t ad = arow + (uint32_t)(wl * 128 +
                                      (((sub * 2 + kc) ^ (wl & 7)) * 16));
                        asm volatile(
                            "ldmatrix.sync.aligned.m8n8.x4.shared.b16 {%0,%1,%2,%3}, [%4];"
                            : "=r"(af[mt][0]), "=r"(af[mt][1]),
                              "=r"(af[mt][2]), "=r"(af[mt][3]) : "r"(ad));
                    }
#pragma unroll
                    for (int mt = 0; mt < 2; mt++)
#pragma unroll
                        for (int nt = 0; nt < 8; nt++)
                            asm volatile(
                                "mma.sync.aligned.m16n8k16.row.col.f32.bf16.bf16.f32 "
                                "{%0,%1,%2,%3}, {%4,%5,%6,%7}, {%8,%9}, {%0,%1,%2,%3};"
                                : "+f"(acc[mt][nt][0]), "+f"(acc[mt][nt][1]),
                                  "+f"(acc[mt][nt][2]), "+f"(acc[mt][nt][3])
                                : "r"(af[mt][0]), "r"(af[mt][1]),
                                  "r"(af[mt][2]), "r"(af[mt][3]),
                                  "r"(bf[nt][0]), "r"(bf[nt][1]));
                }
            }
        }

        // Epilogue: y = D[hi,Wh] + D[hi,Wl] + D[lo,Wh].
#define FRAG_LOOP(...)                                                         \
        _Pragma("unroll")                                                      \
        for (int mt = 0; mt < 2; mt++) {                                       \
            int r0 = pbase + mt * 16 + (lane >> 2);                            \
            _Pragma("unroll")                                                  \
            for (int nt = 0; nt < 8; nt++) {                                   \
                int c = nt * 8 + (lane & 3) * 2;                               \
                float* q0 = &Ds[r0 * 68 + c];                                  \
                float* q1 = &Ds[(r0 + 8) * 68 + c];                            \
                __VA_ARGS__;                                                   \
            }                                                                  \
        }
        if (wm < 2 && wn == 0)   // hi x Wh : plain store
            FRAG_LOOP(*(float2*)q0 = make_float2(acc[mt][nt][0], acc[mt][nt][1]);
                      *(float2*)q1 = make_float2(acc[mt][nt][2], acc[mt][nt][3]));
        __syncthreads();
        if ((wm < 2 && wn == 1) || (wm >= 2 && wn == 0))  // both adds concurrent
            FRAG_LOOP(atomicAdd(q0, acc[mt][nt][0]);
                      atomicAdd(q0 + 1, acc[mt][nt][1]);
                      atomicAdd(q1, acc[mt][nt][2]);
                      atomicAdd(q1 + 1, acc[mt][nt][3]));
        __syncthreads();

        // Store: thread t -> o = t/4, px chunk (t%4)*16, 8 float2 per thread.
        {
            int o = tid >> 2, px0 = (tid & 3) * 16;
            float bv = bias[o];
            float* op = out + (((size_t)(b * 64 + o)) * HO + h) * WO + w0 + px0;
#pragma unroll
            for (int q = 0; q < 16; q += 2) {
                float2 v;
                v.x = Ds[(px0 + q) * 68 + o] + bv;
                v.y = Ds[(px0 + q + 1) * 68 + o] + bv;
                *(float2*)(op + q) = v;
            }
        }
        __syncthreads();   // Dstage free before next row
    }
}

// ---------------------------------------------------------------------------
extern "C" void kernel_launch(void* const* d_in, const int* in_sizes, int n_in,
                              void* d_out, int out_size) {
    const float* x    = (const float*)d_in[0];
    const float* w    = (const float*)d_in[1];
    const float* bias = (const float*)d_in[2];
    const int*   cin  = (const int*)d_in[3];
    const int*   cout = (const int*)d_in[4];
    int K = in_sizes[3];
    int B = in_sizes[0] / (64 * 192 * 192);

    cudaFuncSetAttribute(conv_mma, cudaFuncAttributeMaxDynamicSharedMemorySize,
                         SMEM_TOTAL);

    k_zero<<<(64 * 9 * 64 + 1023) / 1024, 1024>>>();
    k_scatter<<<(K + 255) / 256, 256>>>(w, cin, cout, K);
    k_buildB<<<(18432 + 255) / 256, 256>>>();
    dim3 tg(192, B);
    k_transpose<<<tg, 256>>>(x);
    dim3 grid(3, 19, B);
    conv_mma<<<grid, 256, SMEM_TOTAL>>>(bias, (float*)d_out);
}

// round 17
// speedup vs baseline: 1.3232x; 1.2589x over previous
#include <cuda_runtime.h>
#include <cuda_bf16.h>
#include <cstdint>

#define HO 190
#define WO 190
#define XROW 8448                 // 66 cols x 128B per (slot,pass) row
#define XS_BYTES (4 * 2 * XROW)   // 67584
#define DS_OFF XS_BYTES
#define SMEM_TOTAL (DS_OFF + 64 * 68 * 4)   // 84992 B -> 2 CTAs/SM

typedef unsigned long long ull;

__device__ float g_Wd[64 * 9 * 64];                     // [o][tap][i]
__device__ __align__(16) unsigned g_B[36 * 16 * 32 * 2]; // b-frags, reg order
__device__ __align__(16) __nv_bfloat16 g_xh[4ull * 192 * 192 * 64]; // [b][h][w][i]
__device__ __align__(16) __nv_bfloat16 g_xl[4ull * 192 * 192 * 64];

__device__ __forceinline__ void cpa16(uint32_t d, const void* s) {
    asm volatile("cp.async.ca.shared.global [%0], [%1], 16;" :: "r"(d), "l"(s));
}
#define CPCOMMIT() asm volatile("cp.async.commit_group;")
#define CPWAIT0()  asm volatile("cp.async.wait_group 0;")

// ------------------------- prep kernels -------------------------
__global__ void k_zero() {
    int i = blockIdx.x * 1024 + threadIdx.x;
    if (i < 64 * 9 * 64) g_Wd[i] = 0.0f;
}
__global__ void k_scatter(const float* __restrict__ w, const int* __restrict__ cin,
                          const int* __restrict__ cout, int K) {
    int k = blockIdx.x * 256 + threadIdx.x;
    if (k < K) {
        int o = cout[k], i = cin[k];
#pragma unroll
        for (int t = 0; t < 9; t++)
            atomicAdd(&g_Wd[(o * 9 + t) * 64 + i], w[k * 9 + t]);
    }
}
// B-frags for mma.m16n8k16 (B col-major frag: lane holds n = lane/4,
// k = kstep*16 + (lane%4)*2 (+1), reg1 at k+8). nt 0-7 -> bf16-hi(W), 8-15 -> lo.
__global__ void k_buildB() {
    int idx = blockIdx.x * 256 + threadIdx.x;   // 36*16*32 = 18432
    if (idx >= 18432) return;
    int lane = idx & 31, nt = (idx >> 5) & 15, ks = idx >> 9;
    int n = nt * 8 + (lane >> 2);
    int o = n & 63;
    bool lo = n >= 64;
    int kk = ks * 16 + (lane & 3) * 2;
#pragma unroll
    for (int rr = 0; rr < 2; rr++) {
        unsigned pk = 0;
#pragma unroll
        for (int e = 0; e < 2; e++) {
            int k = kk + rr * 8 + e;
            int tap = k >> 6, i = k & 63;
            float v = g_Wd[(o * 9 + tap) * 64 + i];
            __nv_bfloat16 h = __float2bfloat16(v);
            __nv_bfloat16 val = lo ? __float2bfloat16(v - __bfloat162float(h)) : h;
            pk |= (unsigned)__bfloat16_as_ushort(val) << (16 * e);
        }
        g_B[idx * 2 + rr] = pk;
    }
}
// x -> channel-last bf16 hi/lo with coalesced output via smem staging.
// Staging stride 144B (4-way STS conflict, acceptable; STG fully coalesced).
__global__ void k_transpose(const float* __restrict__ x) {
    __shared__ __align__(16) float sm[64 * 192];   // 48 KB, reused as staging
    int h = blockIdx.x, b = blockIdx.y, t = threadIdx.x;
    for (int idx = t; idx < 64 * 192; idx += 256) {
        int i = idx / 192, w = idx % 192;
        sm[idx] = x[(((size_t)b * 64 + i) * 192 + h) * 192 + w];
    }
    __syncthreads();
    unsigned hv[32], lv[32];
    if (t < 192) {
#pragma unroll
        for (int q = 0; q < 32; q++) {
            float f0 = sm[(2 * q) * 192 + t], f1 = sm[(2 * q + 1) * 192 + t];
            __nv_bfloat16 h0 = __float2bfloat16(f0), h1 = __float2bfloat16(f1);
            __nv_bfloat16 l0 = __float2bfloat16(f0 - __bfloat162float(h0));
            __nv_bfloat16 l1 = __float2bfloat16(f1 - __bfloat162float(h1));
            hv[q] = (unsigned)__bfloat16_as_ushort(h0) | ((unsigned)__bfloat16_as_ushort(h1) << 16);
            lv[q] = (unsigned)__bfloat16_as_ushort(l0) | ((unsigned)__bfloat16_as_ushort(l1) << 16);
        }
    }
    __syncthreads();              // all reads of sm done before overwrite
    char* st = (char*)sm;         // staging: 192 px x 144B = 27648 B
    // hi pass
    if (t < 192) {
#pragma unroll
        for (int q = 0; q < 8; q++)
            *(uint4*)(st + t * 144 + q * 16) =
                make_uint4(hv[4*q], hv[4*q+1], hv[4*q+2], hv[4*q+3]);
    }
    __syncthreads();
    {
        uint4* dst = (uint4*)(g_xh + (((size_t)b * 192 + h) * 192) * 64);
        for (int u = t; u < 1536; u += 256) {
            int px = u >> 3, q = u & 7;
            dst[u] = *(uint4*)(st + px * 144 + q * 16);
        }
    }
    __syncthreads();
    // lo pass
    if (t < 192) {
#pragma unroll
        for (int q = 0; q < 8; q++)
            *(uint4*)(st + t * 144 + q * 16) =
                make_uint4(lv[4*q], lv[4*q+1], lv[4*q+2], lv[4*q+3]);
    }
    __syncthreads();
    {
        uint4* dst = (uint4*)(g_xl + (((size_t)b * 192 + h) * 192) * 64);
        for (int u = t; u < 1536; u += 256) {
            int px = u >> 3, q = u & 7;
            dst[u] = *(uint4*)(st + px * 144 + q * 16);
        }
    }
}

// ------------------------- conv kernel -------------------------
// grid (3, 19, 4). GEMM M=64 px, N=64 o, K=3x576 (xh*Wh + xh*Wl + xl*Wh all
// accumulated in ONE warp's registers -> no cross-warp reduction, no atomics).
// 8 warps: wm=warp>>1 -> m16 px strip; wn=warp&1 -> n32 o half.
__global__ __launch_bounds__(256, 2)
void conv_mma(const float* __restrict__ bias, float* __restrict__ out) {
    extern __shared__ __align__(16) char smem[];
    uint32_t sb = (uint32_t)__cvta_generic_to_shared(smem);
    int tid = threadIdx.x, lane = tid & 31, warp = tid >> 5;
    int wm = warp >> 1, wn = warp & 1;
    int pbase = wm * 16;                      // px base (0..48)
    int obase = wn * 32;                      // o base (0 or 32)

    int b = blockIdx.z, h0 = blockIdx.y * 10;
    int w0 = (blockIdx.x == 0) ? 0 : (blockIdx.x == 1 ? 64 : 126);

    const __nv_bfloat16* xh = g_xh + (size_t)b * 192 * 192 * 64;
    const __nv_bfloat16* xl = g_xl + (size_t)b * 192 * 192 * 64;
    const uint2* gB2 = (const uint2*)g_B;     // frag (ks,nt): 32 lanes x 8B

#define STAGE(hh) do {                                                         \
        int _s = (hh) & 3;                                                     \
        const __nv_bfloat16* s0 = xh + (((size_t)(hh)) * 192 + w0) * 64;       \
        const __nv_bfloat16* s1 = xl + (((size_t)(hh)) * 192 + w0) * 64;       \
        for (int cc = tid; cc < 528; cc += 256) {                              \
            int ws_ = cc >> 3, j = cc & 7;                                     \
            uint32_t dof = (uint32_t)(ws_ * 128 + ((j ^ (ws_ & 7)) * 16));     \
            cpa16(sb + (uint32_t)((_s * 2 + 0) * XROW) + dof,                  \
                  (const char*)s0 + ws_ * 128 + j * 16);                       \
            cpa16(sb + (uint32_t)((_s * 2 + 1) * XROW) + dof,                  \
                  (const char*)s1 + ws_ * 128 + j * 16);                       \
        } } while (0)

    STAGE(h0); STAGE(h0 + 1); STAGE(h0 + 2);
    CPCOMMIT();

    float* Ds = (float*)(smem + DS_OFF);     // [64 px][68] fp32

    for (int r = 0; r < 10; r++) {
        int h = h0 + r;
        CPWAIT0();
        __syncthreads();
        if (r < 9) STAGE(h + 3);             // overwrites slot (h-1)&3 (free)
        CPCOMMIT();

        float acc[4][4];
#pragma unroll
        for (int j = 0; j < 4; j++)
#pragma unroll
            for (int e = 0; e < 4; e++) acc[j][e] = 0.0f;

#pragma unroll
        for (int tap = 0; tap < 9; tap++) {
            const int dh = tap / 3, dw = tap % 3;
            int slot = (h + dh) & 3;
            uint32_t arow_h = sb + (uint32_t)((slot * 2 + 0) * XROW);
            uint32_t arow_l = sb + (uint32_t)((slot * 2 + 1) * XROW);
#pragma unroll
            for (int sub = 0; sub < 4; sub++) {
                int ks = tap * 4 + sub;
                // B frags: Wh (nt=wn*4+j) and Wl (nt=8+wn*4+j), from L2.
                unsigned bh[4][2], bl[4][2];
#pragma unroll
                for (int j = 0; j < 4; j++) {
                    uint2 v0 = __ldg(&gB2[(size_t)(ks * 16 + wn * 4 + j) * 32 + lane]);
                    uint2 v1 = __ldg(&gB2[(size_t)(ks * 16 + 8 + wn * 4 + j) * 32 + lane]);
                    bh[j][0] = v0.x; bh[j][1] = v0.y;
                    bl[j][0] = v1.x; bl[j][1] = v1.y;
                }
                // A frags: one m16k16 ldmatrix per pass.
                int px = pbase + (lane & 15);
                int wl_ = px + dw;
                int kc = lane >> 4;
                uint32_t aoff = (uint32_t)(wl_ * 128 +
                                (((sub * 2 + kc) ^ (wl_ & 7)) * 16));
                unsigned ah[4], al[4];
                asm volatile(
                    "ldmatrix.sync.aligned.m8n8.x4.shared.b16 {%0,%1,%2,%3}, [%4];"
                    : "=r"(ah[0]), "=r"(ah[1]), "=r"(ah[2]), "=r"(ah[3])
                    : "r"(arow_h + aoff));
                asm volatile(
                    "ldmatrix.sync.aligned.m8n8.x4.shared.b16 {%0,%1,%2,%3}, [%4];"
                    : "=r"(al[0]), "=r"(al[1]), "=r"(al[2]), "=r"(al[3])
                    : "r"(arow_l + aoff));
#define MMA(ACC, A, B)                                                         \
                asm volatile(                                                  \
                    "mma.sync.aligned.m16n8k16.row.col.f32.bf16.bf16.f32 "     \
                    "{%0,%1,%2,%3}, {%4,%5,%6,%7}, {%8,%9}, {%0,%1,%2,%3};"    \
                    : "+f"((ACC)[0]), "+f"((ACC)[1]), "+f"((ACC)[2]), "+f"((ACC)[3]) \
                    : "r"((A)[0]), "r"((A)[1]), "r"((A)[2]), "r"((A)[3]),      \
                      "r"((B)[0]), "r"((B)[1]))
#pragma unroll
                for (int j = 0; j < 4; j++) MMA(acc[j], ah, bh[j]);
#pragma unroll
                for (int j = 0; j < 4; j++) MMA(acc[j], ah, bl[j]);
#pragma unroll
                for (int j = 0; j < 4; j++) MMA(acc[j], al, bh[j]);
            }
        }

        // Epilogue: each warp owns disjoint (px, o) tile -> plain stores.
        {
            int r0 = pbase + (lane >> 2);
#pragma unroll
            for (int j = 0; j < 4; j++) {
                int c = obase + j * 8 + (lane & 3) * 2;
                *(float2*)&Ds[r0 * 68 + c] = make_float2(acc[j][0], acc[j][1]);
                *(float2*)&Ds[(r0 + 8) * 68 + c] = make_float2(acc[j][2], acc[j][3]);
            }
        }
        __syncthreads();

        // Store: thread t -> o = t/4, px chunk (t%4)*16, 8 float2 per thread.
        {
            int o = tid >> 2, px0 = (tid & 3) * 16;
            float bv = bias[o];
            float* op = out + (((size_t)(b * 64 + o)) * HO + h) * WO + w0 + px0;
#pragma unroll
            for (int q = 0; q < 16; q += 2) {
                float2 v;
                v.x = Ds[(px0 + q) * 68 + o] + bv;
                v.y = Ds[(px0 + q + 1) * 68 + o] + bv;
                *(float2*)(op + q) = v;
            }
        }
        __syncthreads();   // Dstage free before next row
    }
}

// ---------------------------------------------------------------------------
extern "C" void kernel_launch(void* const* d_in, const int* in_sizes, int n_in,
                              void* d_out, int out_size) {
    const float* x    = (const float*)d_in[0];
    const float* w    = (const float*)d_in[1];
    const float* bias = (const float*)d_in[2];
    const int*   cin  = (const int*)d_in[3];
    const int*   cout = (const int*)d_in[4];
    int K = in_sizes[3];
    int B = in_sizes[0] / (64 * 192 * 192);

    cudaFuncSetAttribute(conv_mma, cudaFuncAttributeMaxDynamicSharedMemorySize,
                         SMEM_TOTAL);

    k_zero<<<(64 * 9 * 64 + 1023) / 1024, 1024>>>();
    k_scatter<<<(K + 255) / 256, 256>>>(w, cin, cout, K);
    k_buildB<<<(18432 + 255) / 256, 256>>>();
    dim3 tg(192, B);
    k_transpose<<<tg, 256>>>(x);
    dim3 grid(3, 19, B);
    conv_mma<<<grid, 256, SMEM_TOTAL>>>(bias, (float*)d_out);
}